// round 7
// baseline (speedup 1.0000x reference)
#include <cuda_runtime.h>
#include <cstdint>

typedef unsigned long long ull;

#define NB 128
#define NT 4096
#define K1_NTH 256
#define NCHUNK 4            // CTAs per batch
#define TOKC 1024           // tokens per CTA

__device__ float g_scratch[NB * NCHUNK * 18];   // [cta][lmax, sum, ctx16]

__device__ __forceinline__ float ex2f_(float x) {
    float y; asm("ex2.approx.f32 %0, %1;" : "=f"(y) : "f"(x)); return y;
}
__device__ __forceinline__ float rcpf_(float x) {
    float y; asm("rcp.approx.f32 %0, %1;" : "=f"(y) : "f"(x)); return y;
}
__device__ __forceinline__ float tanhf_(float x) {
    float y; asm("tanh.approx.f32 %0, %1;" : "=f"(y) : "f"(x)); return y;
}
__device__ __forceinline__ void pfma(ull& d, ull a, ull b) {
    asm("fma.rn.f32x2 %0, %1, %2, %0;" : "+l"(d) : "l"(a), "l"(b));
}
__device__ __forceinline__ ull pack2(float a, float b) {
    ull p; asm("mov.b64 %0, {%1, %2};" : "=l"(p) : "f"(a), "f"(b)); return p;
}
__device__ __forceinline__ float2 unpack2(ull p) {
    float2 r; asm("mov.b64 {%0, %1}, %2;" : "=f"(r.x), "=f"(r.y) : "l"(p)); return r;
}

// ================== K1: partial softmax over 1024 tokens ==================
__global__ void __launch_bounds__(K1_NTH, 4)
attn_partial(const float* __restrict__ query,   // [B,1,16]
             const float* __restrict__ key,     // [B,T,16]
             const float* __restrict__ value,   // [B,T,16]
             const float* __restrict__ W1,      // [32,16]
             const float* __restrict__ W2,      // [32,16]
             const float* __restrict__ bias,    // scalar
             const float* __restrict__ v_w,     // [1,32]
             const float* __restrict__ v_b,     // [1]
             float* __restrict__ out_attn)      // [B,T] (unnormalized e)
{
    const int cta   = blockIdx.x;
    const int b     = cta >> 2;
    const int base  = (cta & 3) * TOKC;
    const int tid   = threadIdx.x;
    const int lane  = tid & 31;
    const int wid   = tid >> 5;

    __shared__ ull        sW2p[32 * 8];
    __shared__ ulonglong2 scv[32];        // .x = (qproj_w + bias, 0), .y lo = v_w[w]
    __shared__ float      sred[8 * 17];
    __shared__ float      sbc[1];         // local max broadcast

    if (tid < 128) {
        float4 wr = reinterpret_cast<const float4*>(W2)[tid];
        sW2p[tid * 2 + 0] = pack2(wr.x, wr.y);
        sW2p[tid * 2 + 1] = pack2(wr.z, wr.w);
    }
    if (tid >= 128 && tid < 160) {
        const int w = tid - 128;
        float acc = *bias;
        #pragma unroll
        for (int d = 0; d < 16; d++)
            acc = fmaf(query[b * 16 + d], W1[w * 16 + d], acc);
        scv[w].x = pack2(acc, 0.0f);
        scv[w].y = pack2(v_w[w], 0.0f);
    }
    __syncthreads();

    const float vb = *v_b;

    // ---------- Phase A: scores for 4 tokens (2 per pass) ----------
    float s[4];
    #pragma unroll
    for (int jp = 0; jp < 2; jp++) {
        const int t0 = base + tid + (2 * jp + 0) * K1_NTH;
        const int t1 = base + tid + (2 * jp + 1) * K1_NTH;
        const ulonglong2* kp0 =
            reinterpret_cast<const ulonglong2*>(key + ((size_t)b * NT + t0) * 16);
        const ulonglong2* kp1 =
            reinterpret_cast<const ulonglong2*>(key + ((size_t)b * NT + t1) * 16);
        ull ka[8], kb[8];
        #pragma unroll
        for (int i = 0; i < 4; i++) {
            ulonglong2 va = kp0[i]; ka[2*i] = va.x; ka[2*i+1] = va.y;
            ulonglong2 vb_ = kp1[i]; kb[2*i] = vb_.x; kb[2*i+1] = vb_.y;
        }

        float a0 = vb, a1 = vb;
        #pragma unroll 4
        for (int w = 0; w < 32; w++) {
            const ulonglong2 cc = scv[w];
            ull acc0 = cc.x;
            ull acc1 = cc.x;
            const float vw = unpack2(cc.y).x;
            const ulonglong2* wr =
                reinterpret_cast<const ulonglong2*>(&sW2p[w * 8]);
            ulonglong2 wv = wr[0];
            pfma(acc0, ka[0], wv.x); pfma(acc1, kb[0], wv.x);
            pfma(acc0, ka[1], wv.y); pfma(acc1, kb[1], wv.y);
            wv = wr[1];
            pfma(acc0, ka[2], wv.x); pfma(acc1, kb[2], wv.x);
            pfma(acc0, ka[3], wv.y); pfma(acc1, kb[3], wv.y);
            wv = wr[2];
            pfma(acc0, ka[4], wv.x); pfma(acc1, kb[4], wv.x);
            pfma(acc0, ka[5], wv.y); pfma(acc1, kb[5], wv.y);
            wv = wr[3];
            pfma(acc0, ka[6], wv.x); pfma(acc1, kb[6], wv.x);
            pfma(acc0, ka[7], wv.y); pfma(acc1, kb[7], wv.y);

            const float2 h0 = unpack2(acc0);
            const float2 h1 = unpack2(acc1);
            const float t0h = tanhf_(h0.x + h0.y);
            const float t1h = tanhf_(h1.x + h1.y);
            a0 = fmaf(vw, t0h, a0);
            a1 = fmaf(vw, t1h, a1);
        }
        s[2 * jp + 0] = a0;
        s[2 * jp + 1] = a1;
    }

    // ---------- CTA-local max (8 warps) ----------
    float m = fmaxf(fmaxf(s[0], s[1]), fmaxf(s[2], s[3]));
    #pragma unroll
    for (int o = 16; o > 0; o >>= 1)
        m = fmaxf(m, __shfl_xor_sync(0xffffffffu, m, o));
    if (lane == 0) sred[wid] = m;
    __syncthreads();
    if (wid == 0) {
        float mm = (lane < 8) ? sred[lane] : -3.4e38f;
        #pragma unroll
        for (int o = 16; o > 0; o >>= 1)
            mm = fmaxf(mm, __shfl_xor_sync(0xffffffffu, mm, o));
        if (lane == 0) sbc[0] = mm;
    }
    __syncthreads();
    const float lmax  = sbc[0];
    const float L     = 1.4426950408889634f;
    const float negmL = -lmax * L;

    // ---------- Phase B: e + weighted value accumulation ----------
    float csum = 0.0f;
    ull cv[8];
    #pragma unroll
    for (int i = 0; i < 8; i++) cv[i] = 0ull;

    #pragma unroll
    for (int j = 0; j < 4; j++) {
        const int t = base + tid + j * K1_NTH;
        const float e = ex2f_(fmaf(s[j], L, negmL));
        csum += e;
        out_attn[(size_t)b * NT + t] = e;       // unnormalized; K2 rescales
        const ull ee = pack2(e, e);
        const ulonglong2* vp =
            reinterpret_cast<const ulonglong2*>(value + ((size_t)b * NT + t) * 16);
        #pragma unroll
        for (int i = 0; i < 4; i++) {
            ulonglong2 vv = vp[i];
            pfma(cv[2*i],   ee, vv.x);
            pfma(cv[2*i+1], ee, vv.y);
        }
    }

    float cvf[16];
    #pragma unroll
    for (int i = 0; i < 8; i++) {
        float2 u = unpack2(cv[i]);
        cvf[2*i] = u.x; cvf[2*i+1] = u.y;
    }

    // ---------- Deterministic 17-value reduction over 8 warps ----------
    #pragma unroll
    for (int o = 16; o > 0; o >>= 1) {
        csum += __shfl_xor_sync(0xffffffffu, csum, o);
        #pragma unroll
        for (int i = 0; i < 16; i++)
            cvf[i] += __shfl_xor_sync(0xffffffffu, cvf[i], o);
    }
    if (lane == 0) {
        sred[wid * 17] = csum;
        #pragma unroll
        for (int i = 0; i < 16; i++) sred[wid * 17 + 1 + i] = cvf[i];
    }
    __syncthreads();
    if (tid < 17) {
        float a = sred[tid];
        #pragma unroll
        for (int w = 1; w < 8; w++) a += sred[w * 17 + tid];
        g_scratch[cta * 18 + 1 + tid] = a;      // sum, ctx[16]
    }
    if (tid == 17) g_scratch[cta * 18] = lmax;
}

// ================== K2: combine + rescale (one block per K1 chunk) ==================
__global__ void __launch_bounds__(256)
attn_combine(float* __restrict__ out_ctx,       // [B,16]
             float* __restrict__ out_attn)      // [B,T]
{
    const int c     = blockIdx.x;     // 0..511
    const int b     = c >> 2;
    const int chunk = c & 3;
    const int tid   = threadIdx.x;

    // Issue this thread's attn float4 load FIRST so DRAM latency overlaps
    // the factor computation below.
    float4* ap = reinterpret_cast<float4*>(out_attn + (size_t)b * NT)
                 + chunk * 256;
    float4 v = ap[tid];

    __shared__ float f[4];            // normalized chunk factors c_i / total
    if (tid == 0) {
        const float* gs = g_scratch + b * (NCHUNK * 18);
        const float l0 = gs[0], l1 = gs[18], l2 = gs[36], l3 = gs[54];
        const float gmax = fmaxf(fmaxf(l0, l1), fmaxf(l2, l3));
        const float L = 1.4426950408889634f;
        const float c0 = ex2f_((l0 - gmax) * L);
        const float c1 = ex2f_((l1 - gmax) * L);
        const float c2 = ex2f_((l2 - gmax) * L);
        const float c3 = ex2f_((l3 - gmax) * L);
        const float total = gs[1]*c0 + gs[19]*c1 + gs[37]*c2 + gs[55]*c3;
        const float inv = rcpf_(total);
        f[0] = c0 * inv; f[1] = c1 * inv; f[2] = c2 * inv; f[3] = c3 * inv;
    }
    __syncthreads();

    if (chunk == 0 && tid < 16) {
        const float* gs = g_scratch + b * (NCHUNK * 18);
        out_ctx[b * 16 + tid] = gs[2 + tid]  * f[0] + gs[20 + tid] * f[1]
                              + gs[38 + tid] * f[2] + gs[56 + tid] * f[3];
    }

    const float sc = f[chunk];
    v.x *= sc; v.y *= sc; v.z *= sc; v.w *= sc;
    ap[tid] = v;
}

extern "C" void kernel_launch(void* const* d_in, const int* in_sizes, int n_in,
                              void* d_out, int out_size) {
    const float* query = (const float*)d_in[0];
    const float* key   = (const float*)d_in[1];
    const float* value = (const float*)d_in[2];
    const float* W1    = (const float*)d_in[3];
    const float* W2    = (const float*)d_in[4];
    const float* bias  = (const float*)d_in[5];
    const float* v_w   = (const float*)d_in[6];
    const float* v_b   = (const float*)d_in[7];

    float* out_ctx  = (float*)d_out;            // [B,1,16]
    float* out_attn = (float*)d_out + NB * 16;  // [B,T]

    attn_partial<<<NB * NCHUNK, K1_NTH>>>(query, key, value, W1, W2,
                                          bias, v_w, v_b, out_attn);
    attn_combine<<<NB * NCHUNK, 256>>>(out_ctx, out_attn);
}